// round 16
// baseline (speedup 1.0000x reference)
#include <cuda_runtime.h>
#include <cstdint>

#define Hh 256
#define Ww 832
#define Bb 16
#define Cc 3
#define HW (Hh * Ww)                     // 212992
#define PPT 4                            // pixels per thread (warp-strided)
#define TPB 256
#define PIX_PER_BLOCK (TPB * PPT)        // 1024
#define BLOCKS_PER_BATCH (HW / PIX_PER_BLOCK)  // 208

__device__ __forceinline__ void mm3(const float* A, const float* B, float* C) {
    #pragma unroll
    for (int r = 0; r < 3; r++)
        #pragma unroll
        for (int c = 0; c < 3; c++)
            C[r * 3 + c] = A[r * 3 + 0] * B[0 * 3 + c]
                         + A[r * 3 + 1] * B[1 * 3 + c]
                         + A[r * 3 + 2] * B[2 * 3 + c];
}

__device__ __forceinline__ void gather16(const float* __restrict__ xc,
                                         const int off[PPT][4], float t[16]) {
    #pragma unroll
    for (int p = 0; p < PPT; p++) {
        t[p * 4 + 0] = __ldg(xc + off[p][0]);
        t[p * 4 + 1] = __ldg(xc + off[p][1]);
        t[p * 4 + 2] = __ldg(xc + off[p][2]);
        t[p * 4 + 3] = __ldg(xc + off[p][3]);
    }
}

// write-through stores: output is write-only compulsory traffic; don't let it
// allocate L2 lines at all -> L2 stays dedicated to the gather source x.
__device__ __forceinline__ void blend_store(float* __restrict__ oc,
                                            const float wgt[PPT][4], const float t[16]) {
    #pragma unroll
    for (int p = 0; p < PPT; p++) {
        float v = fmaf(wgt[p][0], t[p * 4 + 0],
                  fmaf(wgt[p][1], t[p * 4 + 1],
                  fmaf(wgt[p][2], t[p * 4 + 2],
                       wgt[p][3] * t[p * 4 + 3])));
        __stwt(oc + p * TPB, v);
    }
}

__global__ __launch_bounds__(TPB) void reconstructor_kernel(
    const float* __restrict__ x,
    const float* __restrict__ depth,
    const float* __restrict__ pose,
    const float* __restrict__ intr,
    const float* __restrict__ intr_inv,
    float* __restrict__ out)
{
    __shared__ float sA[9];
    __shared__ float sb[3];

    const int b = blockIdx.x / BLOCKS_PER_BATCH;

    if (threadIdx.x == 0) {
        const float* p = pose + b * 6;
        const float tx = p[0], ty = p[1], tz = p[2];
        const float ax = p[3], ay = p[4], az = p[5];
        const float cz = cosf(az), sz = sinf(az);
        const float cy = cosf(ay), sy = sinf(ay);
        const float cx = cosf(ax), sx = sinf(ax);
        float Zm[9] = { cz, -sz, 0.f,  sz,  cz, 0.f,  0.f, 0.f, 1.f };
        float Ym[9] = { cy, 0.f,  sy,  0.f, 1.f, 0.f, -sy, 0.f,  cy };
        float Xm[9] = { 1.f, 0.f, 0.f, 0.f,  cx, -sx, 0.f,  sx,  cx };
        float YZ[9], R[9], KR[9], A[9];
        mm3(Ym, Zm, YZ);
        mm3(Xm, YZ, R);          // rot = X @ Y @ Z
        const float* K  = intr + b * 9;
        const float* Ki = intr_inv + b * 9;
        mm3(K, R, KR);           // K @ R
        mm3(KR, Ki, A);          // fold: pc = d * (A @ pix) + K @ t
        #pragma unroll
        for (int q = 0; q < 9; q++) sA[q] = A[q];
        sb[0] = K[0] * tx + K[1] * ty + K[2] * tz;
        sb[1] = K[3] * tx + K[4] * ty + K[5] * tz;
        sb[2] = K[6] * tx + K[7] * ty + K[8] * tz;
    }
    __syncthreads();

    // warp-strided: thread t handles pixels blockBase + t + p*TPB
    const int blockBase = (blockIdx.x % BLOCKS_PER_BATCH) * PIX_PER_BLOCK;

    const float a0 = sA[0], a1 = sA[1], a2 = sA[2];
    const float a3 = sA[3], a4 = sA[4], a5 = sA[5];
    const float a6 = sA[6], a7 = sA[7], a8 = sA[8];
    const float b0 = sb[0], b1 = sb[1], b2 = sb[2];

    const float* db = depth + (size_t)b * HW + blockBase + threadIdx.x;
    float dv[PPT];
    #pragma unroll
    for (int p = 0; p < PPT; p++) dv[p] = __ldcs(db + p * TPB);  // read-once stream

    int   off[PPT][4];
    float wgt[PPT][4];

    const float wmax = (float)(Ww - 1);
    const float hmax = (float)(Hh - 1);
    const float nx = 2.0f / (float)(Ww - 1);
    const float ny = 2.0f / (float)(Hh - 1);

    // incremental row/col tracking (stride TPB < Ww -> at most one row step)
    int i = blockBase / Ww;
    int j = blockBase % Ww + threadIdx.x;
    if (j >= Ww) { j -= Ww; i++; }

    #pragma unroll
    for (int p = 0; p < PPT; p++) {
        const float jf  = (float)j;
        const float ifl = (float)i;
        const float d   = dv[p];

        float Xc = fmaf(d, fmaf(a0, jf, fmaf(a1, ifl, a2)), b0);
        float Yc = fmaf(d, fmaf(a3, jf, fmaf(a4, ifl, a5)), b1);
        float Zc = fmaxf(fmaf(d, fmaf(a6, jf, fmaf(a7, ifl, a8)), b2), 1e-20f);

        const float inv = __fdividef(1.0f, Zc);
        float xn = fmaf(Xc * inv, nx, -1.0f);
        float yn = fmaf(Yc * inv, ny, -1.0f);

        // in-bounds flag replaces the reference's xn/yn -> 2.0 remap:
        // remap fired  <=> |n|>1  <=> all four taps end up zero-weighted.
        const bool inb = (fabsf(xn) <= 1.0f) && (fabsf(yn) <= 1.0f);

        float gx = fmaf(xn, (float)Ww * 0.5f, (float)Ww * 0.5f - 0.5f);
        float gy = fmaf(yn, (float)Hh * 0.5f, (float)Hh * 0.5f - 0.5f);

        float x0f = floorf(gx), y0f = floorf(gy);
        float wx1 = gx - x0f, wx0 = 1.0f - wx1;
        float wy1 = gy - y0f, wy0 = 1.0f - wy1;

        // given inb, only one bound per tap is non-trivial
        const bool vx0 = (x0f >= 0.0f);
        const bool vx1 = (x0f <  wmax);
        const bool vy0 = (y0f >= 0.0f);
        const bool vy1 = (y0f <  hmax);

        // clamped coords in float; offsets < 2^24 are fp32-exact
        float x0c = fminf(fmaxf(x0f, 0.0f), wmax);
        float x1c = fminf(fmaxf(x0f + 1.0f, 0.0f), wmax);
        float y0c = fminf(fmaxf(y0f, 0.0f), hmax);
        float y1c = fminf(fmaxf(y0f + 1.0f, 0.0f), hmax);

        float off00f = fmaf(y0c, (float)Ww, x0c);
        float dx  = x1c - x0c;                 // 0 or 1
        float dyf = (y1c - y0c) * (float)Ww;   // 0 or 832

        wgt[p][0] = wx0 * wy0 * (float)(vx0 && vy0 && inb);
        wgt[p][1] = wx1 * wy0 * (float)(vx1 && vy0 && inb);
        wgt[p][2] = wx0 * wy1 * (float)(vx0 && vy1 && inb);
        wgt[p][3] = wx1 * wy1 * (float)(vx1 && vy1 && inb);

        off[p][0] = (int)off00f;
        off[p][1] = (int)(off00f + dx);
        off[p][2] = (int)(off00f + dyf);
        off[p][3] = (int)(off00f + dx + dyf);

        j += TPB;
        if (j >= Ww) { j -= Ww; i++; }
    }

    const float* xb = x + (size_t)b * Cc * HW;
    float* ob = out + (size_t)b * Cc * HW + blockBase + threadIdx.x;

    // software-pipelined channels
    {
        float tA[16], tB[16];
        gather16(xb + 0 * HW, off, tA);
        gather16(xb + 1 * HW, off, tB);
        blend_store(ob + 0 * (size_t)HW, wgt, tA);
        gather16(xb + 2 * HW, off, tA);
        blend_store(ob + 1 * (size_t)HW, wgt, tB);
        blend_store(ob + 2 * (size_t)HW, wgt, tA);
    }
}

extern "C" void kernel_launch(void* const* d_in, const int* in_sizes, int n_in,
                              void* d_out, int out_size)
{
    const float* x        = (const float*)d_in[0];
    const float* depth    = (const float*)d_in[1];
    const float* pose     = (const float*)d_in[2];
    const float* intr     = (const float*)d_in[3];
    const float* intr_inv = (const float*)d_in[4];
    float* out = (float*)d_out;

    const int total_blocks = Bb * BLOCKS_PER_BATCH;  // 16 * 208 = 3328
    reconstructor_kernel<<<total_blocks, TPB>>>(x, depth, pose, intr, intr_inv, out);
}

// round 17
// speedup vs baseline: 1.0491x; 1.0491x over previous
#include <cuda_runtime.h>
#include <cstdint>

#define Hh 256
#define Ww 832
#define Bb 16
#define Cc 3
#define HW (Hh * Ww)                     // 212992
#define PPT 4                            // pixels per thread (warp-strided)
#define TPB 256
#define PIX_PER_BLOCK (TPB * PPT)        // 1024
#define BLOCKS_PER_BATCH (HW / PIX_PER_BLOCK)  // 208

__device__ __forceinline__ void mm3(const float* A, const float* B, float* C) {
    #pragma unroll
    for (int r = 0; r < 3; r++)
        #pragma unroll
        for (int c = 0; c < 3; c++)
            C[r * 3 + c] = A[r * 3 + 0] * B[0 * 3 + c]
                         + A[r * 3 + 1] * B[1 * 3 + c]
                         + A[r * 3 + 2] * B[2 * 3 + c];
}

__device__ __forceinline__ void gather16(const float* __restrict__ xc,
                                         const int off[PPT][4], float t[16]) {
    #pragma unroll
    for (int p = 0; p < PPT; p++) {
        t[p * 4 + 0] = __ldg(xc + off[p][0]);
        t[p * 4 + 1] = __ldg(xc + off[p][1]);
        t[p * 4 + 2] = __ldg(xc + off[p][2]);
        t[p * 4 + 3] = __ldg(xc + off[p][3]);
    }
}

// evict-first stores: output is write-only, keep it OUT of L2's working set
// so the gather source x stays resident. (stwt tested in R16: regressed --
// bypassing L2 write-buffering puts store drain on the critical path.)
__device__ __forceinline__ void blend_store(float* __restrict__ oc,
                                            const float wgt[PPT][4], const float t[16]) {
    #pragma unroll
    for (int p = 0; p < PPT; p++) {
        float v = fmaf(wgt[p][0], t[p * 4 + 0],
                  fmaf(wgt[p][1], t[p * 4 + 1],
                  fmaf(wgt[p][2], t[p * 4 + 2],
                       wgt[p][3] * t[p * 4 + 3])));
        __stcs(oc + p * TPB, v);
    }
}

__global__ __launch_bounds__(TPB) void reconstructor_kernel(
    const float* __restrict__ x,
    const float* __restrict__ depth,
    const float* __restrict__ pose,
    const float* __restrict__ intr,
    const float* __restrict__ intr_inv,
    float* __restrict__ out)
{
    __shared__ float sA[9];
    __shared__ float sb[3];

    const int b = blockIdx.x / BLOCKS_PER_BATCH;

    if (threadIdx.x == 0) {
        const float* p = pose + b * 6;
        const float tx = p[0], ty = p[1], tz = p[2];
        const float ax = p[3], ay = p[4], az = p[5];
        const float cz = cosf(az), sz = sinf(az);
        const float cy = cosf(ay), sy = sinf(ay);
        const float cx = cosf(ax), sx = sinf(ax);
        float Zm[9] = { cz, -sz, 0.f,  sz,  cz, 0.f,  0.f, 0.f, 1.f };
        float Ym[9] = { cy, 0.f,  sy,  0.f, 1.f, 0.f, -sy, 0.f,  cy };
        float Xm[9] = { 1.f, 0.f, 0.f, 0.f,  cx, -sx, 0.f,  sx,  cx };
        float YZ[9], R[9], KR[9], A[9];
        mm3(Ym, Zm, YZ);
        mm3(Xm, YZ, R);          // rot = X @ Y @ Z
        const float* K  = intr + b * 9;
        const float* Ki = intr_inv + b * 9;
        mm3(K, R, KR);           // K @ R
        mm3(KR, Ki, A);          // fold: pc = d * (A @ pix) + K @ t
        #pragma unroll
        for (int q = 0; q < 9; q++) sA[q] = A[q];
        sb[0] = K[0] * tx + K[1] * ty + K[2] * tz;
        sb[1] = K[3] * tx + K[4] * ty + K[5] * tz;
        sb[2] = K[6] * tx + K[7] * ty + K[8] * tz;
    }
    __syncthreads();

    // warp-strided: thread t handles pixels blockBase + t + p*TPB
    const int blockBase = (blockIdx.x % BLOCKS_PER_BATCH) * PIX_PER_BLOCK;

    const float a0 = sA[0], a1 = sA[1], a2 = sA[2];
    const float a3 = sA[3], a4 = sA[4], a5 = sA[5];
    const float a6 = sA[6], a7 = sA[7], a8 = sA[8];
    const float b0 = sb[0], b1 = sb[1], b2 = sb[2];

    const float* db = depth + (size_t)b * HW + blockBase + threadIdx.x;
    float dv[PPT];
    #pragma unroll
    for (int p = 0; p < PPT; p++) dv[p] = __ldcs(db + p * TPB);  // read-once stream

    int   off[PPT][4];
    float wgt[PPT][4];

    const float wmax = (float)(Ww - 1);
    const float hmax = (float)(Hh - 1);
    const float nx = 2.0f / (float)(Ww - 1);
    const float ny = 2.0f / (float)(Hh - 1);

    // incremental row/col tracking (stride TPB < Ww -> at most one row step)
    int i = blockBase / Ww;
    int j = blockBase % Ww + threadIdx.x;
    if (j >= Ww) { j -= Ww; i++; }

    #pragma unroll
    for (int p = 0; p < PPT; p++) {
        const float jf  = (float)j;
        const float ifl = (float)i;
        const float d   = dv[p];

        float Xc = fmaf(d, fmaf(a0, jf, fmaf(a1, ifl, a2)), b0);
        float Yc = fmaf(d, fmaf(a3, jf, fmaf(a4, ifl, a5)), b1);
        float Zc = fmaxf(fmaf(d, fmaf(a6, jf, fmaf(a7, ifl, a8)), b2), 1e-20f);

        const float inv = __fdividef(1.0f, Zc);
        float xn = fmaf(Xc * inv, nx, -1.0f);
        float yn = fmaf(Yc * inv, ny, -1.0f);

        // in-bounds flag replaces the reference's xn/yn -> 2.0 remap:
        // remap fired  <=> |n|>1  <=> all four taps end up zero-weighted.
        const bool inb = (fabsf(xn) <= 1.0f) && (fabsf(yn) <= 1.0f);

        float gx = fmaf(xn, (float)Ww * 0.5f, (float)Ww * 0.5f - 0.5f);
        float gy = fmaf(yn, (float)Hh * 0.5f, (float)Hh * 0.5f - 0.5f);

        float x0f = floorf(gx), y0f = floorf(gy);
        float wx1 = gx - x0f, wx0 = 1.0f - wx1;
        float wy1 = gy - y0f, wy0 = 1.0f - wy1;

        // given inb, only one bound per tap is non-trivial
        const bool vx0 = (x0f >= 0.0f);
        const bool vx1 = (x0f <  wmax);
        const bool vy0 = (y0f >= 0.0f);
        const bool vy1 = (y0f <  hmax);

        // clamped coords in float; offsets < 2^24 are fp32-exact
        float x0c = fminf(fmaxf(x0f, 0.0f), wmax);
        float x1c = fminf(fmaxf(x0f + 1.0f, 0.0f), wmax);
        float y0c = fminf(fmaxf(y0f, 0.0f), hmax);
        float y1c = fminf(fmaxf(y0f + 1.0f, 0.0f), hmax);

        float off00f = fmaf(y0c, (float)Ww, x0c);
        float dx  = x1c - x0c;                 // 0 or 1
        float dyf = (y1c - y0c) * (float)Ww;   // 0 or 832

        wgt[p][0] = wx0 * wy0 * (float)(vx0 && vy0 && inb);
        wgt[p][1] = wx1 * wy0 * (float)(vx1 && vy0 && inb);
        wgt[p][2] = wx0 * wy1 * (float)(vx0 && vy1 && inb);
        wgt[p][3] = wx1 * wy1 * (float)(vx1 && vy1 && inb);

        off[p][0] = (int)off00f;
        off[p][1] = (int)(off00f + dx);
        off[p][2] = (int)(off00f + dyf);
        off[p][3] = (int)(off00f + dx + dyf);

        j += TPB;
        if (j >= Ww) { j -= Ww; i++; }
    }

    const float* xb = x + (size_t)b * Cc * HW;
    float* ob = out + (size_t)b * Cc * HW + blockBase + threadIdx.x;

    // software-pipelined channels: c1 loads issue before c0 stores
    {
        float tA[16], tB[16];
        gather16(xb + 0 * HW, off, tA);
        gather16(xb + 1 * HW, off, tB);
        blend_store(ob + 0 * (size_t)HW, wgt, tA);
        gather16(xb + 2 * HW, off, tA);
        blend_store(ob + 1 * (size_t)HW, wgt, tB);
        blend_store(ob + 2 * (size_t)HW, wgt, tA);
    }
}

extern "C" void kernel_launch(void* const* d_in, const int* in_sizes, int n_in,
                              void* d_out, int out_size)
{
    const float* x        = (const float*)d_in[0];
    const float* depth    = (const float*)d_in[1];
    const float* pose     = (const float*)d_in[2];
    const float* intr     = (const float*)d_in[3];
    const float* intr_inv = (const float*)d_in[4];
    float* out = (float*)d_out;

    const int total_blocks = Bb * BLOCKS_PER_BATCH;  // 16 * 208 = 3328
    reconstructor_kernel<<<total_blocks, TPB>>>(x, depth, pose, intr, intr_inv, out);
}